// round 15
// baseline (speedup 1.0000x reference)
#include <cuda_runtime.h>
#include <cuda_bf16.h>
#include <math.h>
#include <cstdint>

// ---------------------------------------------------------------------------
// TreeGetter: 11-level conv halving tree as implicit GEMM on mma.sync (bf16,
// hi/lo 3-product split). 128-thread CTA (4 warps, 2Mx2N of 64x32 warp tiles),
// block 128x64x32, 2-stage XOR-swizzled buffer, 4 CTAs/SM.
// NEW: split-K reduction FUSED into the conv kernel (last-CTA pattern with
// atomic tile counters) -> no separate reduce launches; M=4096 levels split.
// ---------------------------------------------------------------------------

#define CDIM 768
#define CK   2304
#define NLEV 11
#define BZ   16
#define BM   128
#define BN   64
#define BKC  32
#define NCH  (CK / BKC)      // 72
#define THREADS 128

#define A_BYTES 8192         // 128 rows * 64 B (swizzled, no pad), per plane
#define B_BYTES 4096         // 32 rows * 128 B (swizzled, no pad), per plane
#define STAGE_BYTES (2 * A_BYTES + 2 * B_BYTES)  // 24576
#define SMEM_BYTES (2 * STAGE_BYTES)             // 49152

// ---------------- scratch (device globals; allocation-free rule) ------------
#define MAXE ((long)BZ * 2048 * CDIM)
__device__ __nv_bfloat16 g_xhi[MAXE], g_xlo[MAXE];   // conv1 input splits
__device__ __nv_bfloat16 g_hhi[MAXE], g_hlo[MAXE];   // conv2 input splits
__device__ __nv_bfloat16 g_w1hi[CK * CDIM], g_w1lo[CK * CDIM];
__device__ __nv_bfloat16 g_w2hi[CK * CDIM], g_w2lo[CK * CDIM];
__device__ float g_part[(long)24576 * CDIM];         // split-K partials
__device__ int   g_cnt[1024];                        // per-tile arrival counters

__device__ __forceinline__ void split_bf16(float v, __nv_bfloat16& hi,
                                           __nv_bfloat16& lo) {
    hi = __float2bfloat16(v);
    lo = __float2bfloat16(v - __bfloat162float(hi));
}

__device__ __forceinline__ uint32_t smem_u32(const void* p) {
    uint32_t a;
    asm("{ .reg .u64 t; cvta.to.shared.u64 t, %1; cvt.u32.u64 %0, t; }"
        : "=r"(a) : "l"(p));
    return a;
}
__device__ __forceinline__ void cp_async16(uint32_t dst, const void* src,
                                           bool pred) {
    int sz = pred ? 16 : 0;
    asm volatile("cp.async.cg.shared.global [%0], [%1], 16, %2;"
                 :: "r"(dst), "l"(src), "r"(sz));
}
__device__ __forceinline__ void cp_commit() {
    asm volatile("cp.async.commit_group;");
}
__device__ __forceinline__ void ldsm_x4(uint32_t* r, uint32_t a) {
    asm volatile("ldmatrix.sync.aligned.m8n8.x4.shared.b16 {%0,%1,%2,%3}, [%4];"
                 : "=r"(r[0]), "=r"(r[1]), "=r"(r[2]), "=r"(r[3]) : "r"(a));
}
__device__ __forceinline__ void ldsm_x4_t(uint32_t* r, uint32_t a) {
    asm volatile("ldmatrix.sync.aligned.m8n8.x4.trans.shared.b16 {%0,%1,%2,%3}, [%4];"
                 : "=r"(r[0]), "=r"(r[1]), "=r"(r[2]), "=r"(r[3]) : "r"(a));
}
__device__ __forceinline__ void mma16816(float* d, const uint32_t* a,
                                         const uint32_t* b) {
    asm("mma.sync.aligned.m16n8k16.row.col.f32.bf16.bf16.f32 "
        "{%0,%1,%2,%3}, {%4,%5,%6,%7}, {%8,%9}, {%0,%1,%2,%3};"
        : "+f"(d[0]), "+f"(d[1]), "+f"(d[2]), "+f"(d[3])
        : "r"(a[0]), "r"(a[1]), "r"(a[2]), "r"(a[3]), "r"(b[0]), "r"(b[1]));
}
__device__ __forceinline__ float gelu_exact(float z) {
    return 0.5f * z * (1.f + erff(z * 0.70710678118654752f));
}

// ---------------------------------------------------------------------------
__global__ void prep_weights(const float* __restrict__ w1,
                             const float* __restrict__ w2) {
    int total = CK * CDIM;
    for (int j = blockIdx.x * blockDim.x + threadIdx.x; j < total;
         j += gridDim.x * blockDim.x) {
        int o  = j % CDIM;
        int kg = j / CDIM;
        int d  = kg / CDIM;
        int i  = kg - d * CDIM;
        long src = (long)o * CK + i * 3 + d;   // w[o][i][d]
        split_bf16(w1[src], g_w1hi[j], g_w1lo[j]);
        split_bf16(w2[src], g_w2hi[j], g_w2lo[j]);
    }
}

__global__ void prep_input(const float* __restrict__ seq,
                           const int* __restrict__ lengths) {
    long total = MAXE;
    for (long j = blockIdx.x * (long)blockDim.x + threadIdx.x; j < total;
         j += gridDim.x * (long)blockDim.x) {
        long bp = j / CDIM;
        int p = (int)(bp % 2048);
        int b = (int)(bp / 2048);
        float v = (p < lengths[b]) ? seq[j] : 0.f;
        split_bf16(v, g_xhi[j], g_xlo[j]);
    }
}

__global__ void mask_kernel(float* __restrict__ out,
                            const int* __restrict__ lengths) {
    int idx    = blockIdx.x * blockDim.x + threadIdx.x;
    int stride = gridDim.x * blockDim.x;
    long off = 0;
    int P = 2048;
    for (int lvl = 0; lvl < NLEV; lvl++) {
        int Pout = (P - 1) / 2 + 1;
        long maskOff = off + (long)BZ * Pout * CDIM;
        int n = BZ * Pout;
        for (int i = idx; i < n; i += stride) {
            int b = i / Pout, p = i % Pout;
            int L = lengths[b];
            for (int t = 0; t <= lvl; t++) L = (L - 1) / 2 + 1;
            out[maskOff + i] = (p < L) ? 1.f : 0.f;
        }
        off = maskOff + n;
        P = Pout;
    }
}

// ---------------------------------------------------------------------------
// Implicit-GEMM conv on mma.sync.  128 threads = 4 warps (2M x 2N), warp
// tile 64x32, block 128x64x32, 2-stage XOR-swizzled buffer, 4 CTAs/SM.
// SPLITK: partials to g_part; LAST CTA per output tile (atomic counter)
// performs the reduction + bias/gelu/mask + output writes inline.
template <int STRIDE, bool DO_GELU, bool SPLITK>
__global__ void __launch_bounds__(THREADS, 4)
conv_mma(const float* __restrict__ bias, float* __restrict__ outY,
         int Pin, int Pout, const int* __restrict__ lengths, int level,
         int nspl) {
    extern __shared__ char smem[];
    __shared__ int sIsLast;
    const uint32_t sbase = smem_u32(smem);
    const int tid   = threadIdx.x;
    const int lane  = tid & 31;
    const int wid   = tid >> 5;
    const int warpM = (wid & 1) * 64;
    const int warpN = (wid >> 1) * 32;
    const int p0    = blockIdx.x * BM;
    const int n0    = blockIdx.y * BN;
    const int Mtot  = BZ * Pout;
    const int NC     = SPLITK ? (NCH / nspl) : NCH;
    const int itBase = SPLITK ? (int)blockIdx.z * NC : 0;

    const __nv_bfloat16* Xhi = DO_GELU ? g_xhi : g_hhi;
    const __nv_bfloat16* Xlo = DO_GELU ? g_xlo : g_hlo;
    const __nv_bfloat16* Whi = DO_GELU ? g_w1hi : g_w2hi;
    const __nv_bfloat16* Wlo = DO_GELU ? g_w1lo : g_w2lo;

    float acc[4][4][4];
#pragma unroll
    for (int a = 0; a < 4; a++)
#pragma unroll
        for (int b = 0; b < 4; b++)
#pragma unroll
            for (int c = 0; c < 4; c++) acc[a][b][c] = 0.f;

    // ---- full-masked tile skip ----
    bool anyValid = false;
    {
        int bA = p0 / Pout;
        int bB = (p0 + BM - 1) / Pout;
        if (bB >= BZ) bB = BZ - 1;
        for (int b = bA; b <= bB; b++) {
            int L = lengths[b];
            for (int t = 0; t < level; t++) L = (L - 1) / 2 + 1;
            int lenOut = DO_GELU ? L : ((L - 1) / 2 + 1);
            int pstart = p0 > b * Pout ? p0 - b * Pout : 0;
            if (pstart < lenOut) { anyValid = true; break; }
        }
    }

    if (anyValid) {
        // ---- per-thread load geometry ----
        int aPosB[4]; long aRowBase[4]; bool aOk[4];
        const int akc = tid & 3;
#pragma unroll
        for (int i = 0; i < 4; i++) {
            int r = (tid + i * THREADS) >> 2;
            int grow = p0 + r;
            bool ok = grow < Mtot;
            int b = ok ? grow / Pout : 0;
            int p = grow - b * Pout;
            aOk[i] = ok;
            aPosB[i] = p * STRIDE - 1;
            aRowBase[i] = (long)b * Pin;
        }
        const int bnc = tid & 7;

        auto load_stage = [&](int slot, int it) {
            const uint32_t sa = sbase + slot * STAGE_BYTES;
            const int kk = it * BKC;
            const int d  = (kk >= 1536) ? 2 : (kk >= 768 ? 1 : 0);
            const int c0 = kk - d * CDIM;
#pragma unroll
            for (int i = 0; i < 4; i++) {
                int row = (tid + i * THREADS) >> 2;
                int pos = aPosB[i] + d;
                bool v = aOk[i] && pos >= 0 && pos < Pin;
                long g = v ? ((aRowBase[i] + pos) * CDIM + c0 + akc * 8) : 0;
                uint32_t dst = sa + row * 64 +
                               ((akc ^ ((row >> 1) & 3)) << 4);
                cp_async16(dst, Xhi + g, v);
                cp_async16(dst + A_BYTES, Xlo + g, v);
            }
#pragma unroll
            for (int i = 0; i < 2; i++) {
                int krow = (tid + i * THREADS) >> 3;
                long g = (long)(kk + krow) * CDIM + n0 + bnc * 8;
                uint32_t dst = sa + 2 * A_BYTES + krow * 128 +
                               ((bnc ^ (krow & 7)) << 4);
                cp_async16(dst, Whi + g, true);
                cp_async16(dst + B_BYTES, Wlo + g, true);
            }
            cp_commit();
        };

        const int alr = lane & 15;    // row-within-16 for A ldsm
        const int ahc = lane >> 4;    // chunk half-select
        uint32_t bh[2][4], bl[2][4];

        auto ldsm_b = [&](uint32_t sa, int ks) {
            int krow = ks + alr;
            uint32_t rb = sa + 2 * A_BYTES + krow * 128;
            int cb = (warpN >> 3) + ahc;
#pragma unroll
            for (int np = 0; np < 2; np++) {
                int c = cb + np * 2;
                uint32_t ad = rb + (((c ^ (krow & 7))) << 4);
                ldsm_x4_t(bh[np], ad);
                ldsm_x4_t(bl[np], ad + B_BYTES);
            }
        };
        auto do_mt = [&](uint32_t sa, int mt, int ks) {
            int row = warpM + alr + mt * 16;
            int chunk = ((ks >> 4) << 1) + ahc;
            uint32_t ad = sa + row * 64 + ((chunk ^ ((row >> 1) & 3)) << 4);
            uint32_t ah[4], al[4];
            ldsm_x4(ah, ad);
            ldsm_x4(al, ad + A_BYTES);
#pragma unroll
            for (int nt = 0; nt < 4; nt++)
                mma16816(acc[mt][nt], ah, &bh[nt >> 1][(nt & 1) * 2]);
#pragma unroll
            for (int nt = 0; nt < 4; nt++)
                mma16816(acc[mt][nt], ah, &bl[nt >> 1][(nt & 1) * 2]);
#pragma unroll
            for (int nt = 0; nt < 4; nt++)
                mma16816(acc[mt][nt], al, &bh[nt >> 1][(nt & 1) * 2]);
        };

        // ---- prologue (NC >= 2 always) ----
        load_stage(0, itBase + 0);
        load_stage(1, itBase + 1);

        // ---- main loop ----
#pragma unroll 1
        for (int li = 0; li < NC; li++) {
            asm volatile("cp.async.wait_group %0;" :: "n"(1));
            __syncthreads();
            const uint32_t sa = sbase + (li & 1) * STAGE_BYTES;
            ldsm_b(sa, 0);
#pragma unroll
            for (int mt = 0; mt < 4; mt++) do_mt(sa, mt, 0);
            ldsm_b(sa, 16);
#pragma unroll
            for (int mt = 0; mt < 4; mt++) do_mt(sa, mt, 16);
            __syncthreads();
            if (li + 2 < NC) load_stage(li & 1, itBase + li + 2);
            else cp_commit();
        }
    }

    // ---- epilogue ----
    const int mrow0 = p0 + warpM + (lane >> 2);
    const int colb  = n0 + warpN + 2 * (lane & 3);

    if (SPLITK) {
        // 1) store raw partials (skip if fully masked; reducer writes zeros)
        if (anyValid) {
            float* plane = g_part + (long)blockIdx.z * Mtot * CDIM;
#pragma unroll
            for (int mt = 0; mt < 4; mt++)
#pragma unroll
                for (int half = 0; half < 2; half++) {
                    int row = mrow0 + mt * 16 + half * 8;
                    if (row >= Mtot) continue;
                    long base = (long)row * CDIM;
#pragma unroll
                    for (int nt = 0; nt < 4; nt++) {
                        int col = colb + nt * 8;
                        *(float2*)(plane + base + col) = make_float2(
                            acc[mt][nt][half * 2], acc[mt][nt][half * 2 + 1]);
                    }
                }
        }
        // 2) arrive; last CTA of this tile reduces
        __threadfence();
        const int tileIdx = (int)(blockIdx.x * gridDim.y + blockIdx.y);
        if (tid == 0) {
            int t = atomicAdd(&g_cnt[tileIdx], 1);
            sIsLast = (t == nspl - 1);
        }
        __syncthreads();
        if (!sIsLast) return;
        __threadfence();   // make other CTAs' partials visible
        // 3) fused reduce + bias (+gelu) + mask + outputs
        const long plane = (long)Mtot * CDIM;
        for (int idx = tid; idx < BM * (BN / 2); idx += THREADS) {
            int row = p0 + idx / (BN / 2);
            if (row >= Mtot) continue;
            int col = n0 + (idx % (BN / 2)) * 2;
            int b = row / Pout, p = row - b * Pout;
            int L = lengths[b];
            for (int t = 0; t < level; t++) L = (L - 1) / 2 + 1;
            int lenOut = DO_GELU ? L : ((L - 1) / 2 + 1);
            float z0 = 0.f, z1 = 0.f;
            if (anyValid && p < lenOut) {
                long off = (long)row * CDIM + col;
                for (int s = 0; s < nspl; s++) {
                    float2 v = *(const float2*)(g_part + (long)s * plane + off);
                    z0 += v.x;
                    z1 += v.y;
                }
                z0 += __ldg(&bias[col]);
                z1 += __ldg(&bias[col + 1]);
                if (DO_GELU) { z0 = gelu_exact(z0); z1 = gelu_exact(z1); }
            }
            __nv_bfloat162 h2, l2;
            split_bf16(z0, h2.x, l2.x);
            split_bf16(z1, h2.y, l2.y);
            long base = (long)row * CDIM + col;
            if (DO_GELU) {
                *(__nv_bfloat162*)(g_hhi + base) = h2;
                *(__nv_bfloat162*)(g_hlo + base) = l2;
            } else {
                *(float2*)(outY + base) = make_float2(z0, z1);
                *(__nv_bfloat162*)(g_xhi + base) = h2;
                *(__nv_bfloat162*)(g_xlo + base) = l2;
            }
        }
        __syncthreads();
        if (tid == 0) g_cnt[tileIdx] = 0;   // restore invariant for reuse
        return;
    }

#pragma unroll
    for (int mt = 0; mt < 4; mt++) {
#pragma unroll
        for (int half = 0; half < 2; half++) {
            int row = mrow0 + mt * 16 + half * 8;
            if (row >= Mtot) continue;
            int b = row / Pout;
            int p = row - b * Pout;
            int L = lengths[b];
            for (int t = 0; t < level; t++) L = (L - 1) / 2 + 1;
            int lenOut = DO_GELU ? L : ((L - 1) / 2 + 1);
            bool valid = (p < lenOut) && anyValid;
            long base = (long)row * CDIM;
#pragma unroll
            for (int nt = 0; nt < 4; nt++) {
                int col = colb + nt * 8;
                float z0 = 0.f, z1 = 0.f;
                if (valid) {
                    z0 = acc[mt][nt][half * 2 + 0] + __ldg(&bias[col]);
                    z1 = acc[mt][nt][half * 2 + 1] + __ldg(&bias[col + 1]);
                    if (DO_GELU) { z0 = gelu_exact(z0); z1 = gelu_exact(z1); }
                }
                __nv_bfloat162 h2, l2;
                split_bf16(z0, h2.x, l2.x);
                split_bf16(z1, h2.y, l2.y);
                if (DO_GELU) {
                    *(__nv_bfloat162*)(g_hhi + base + col) = h2;
                    *(__nv_bfloat162*)(g_hlo + base + col) = l2;
                } else {
                    float2 o2 = make_float2(z0, z1);
                    *(float2*)(outY + base + col) = o2;
                    *(__nv_bfloat162*)(g_xhi + base + col) = h2;
                    *(__nv_bfloat162*)(g_xlo + base + col) = l2;
                }
            }
        }
    }
}

// ---------------------------------------------------------------------------
// split depth (capacity ~592 concurrent CTAs, gy = 12). ns must divide 72,
// and NC = 72/ns must be >= 2.
static inline int pick_nspl(int M) {
    if (M > 4096)  return 0;
    if (M == 4096) return 3;     // 1152 CTAs, 2 waves x 24 = 48 (vs 72)
    if (M == 2048) return 3;     // 576 CTAs, path 24
    if (M == 1024) return 6;     // 576 CTAs, path 12
    if (M == 512)  return 12;    // 576 CTAs, path 6
    if (M == 256)  return 24;    // 576 CTAs, path 3
    return 36;                   // M <= 128: path 2
}

extern "C" void kernel_launch(void* const* d_in, const int* in_sizes, int n_in,
                              void* d_out, int out_size) {
    const float* seq     = (const float*)d_in[0];
    const int*   lengths = (const int*)  d_in[1];
    const float* w1      = (const float*)d_in[2];
    const float* b1      = (const float*)d_in[3];
    const float* w2      = (const float*)d_in[4];
    const float* b2      = (const float*)d_in[5];
    float* out = (float*)d_out;

    cudaFuncSetAttribute(conv_mma<1, true, false>,
                         cudaFuncAttributeMaxDynamicSharedMemorySize, SMEM_BYTES);
    cudaFuncSetAttribute(conv_mma<2, false, false>,
                         cudaFuncAttributeMaxDynamicSharedMemorySize, SMEM_BYTES);
    cudaFuncSetAttribute(conv_mma<1, true, true>,
                         cudaFuncAttributeMaxDynamicSharedMemorySize, SMEM_BYTES);
    cudaFuncSetAttribute(conv_mma<2, false, true>,
                         cudaFuncAttributeMaxDynamicSharedMemorySize, SMEM_BYTES);

    prep_weights<<<256, 256>>>(w1, w2);
    prep_input<<<512, 256>>>(seq, lengths);
    mask_kernel<<<64, 256>>>(out, lengths);

    int P = 2048;
    long off = 0;
    for (int lvl = 0; lvl < NLEV; lvl++) {
        int Pout = (P - 1) / 2 + 1;
        // ---- conv1 ----
        int M1 = BZ * P;
        int gx1 = (M1 + BM - 1) / BM;
        int ns1 = pick_nspl(M1);
        if (ns1 == 0) {
            conv_mma<1, true, false><<<dim3(gx1, CDIM / BN), THREADS,
                                       SMEM_BYTES>>>(b1, nullptr, P, P,
                                                     lengths, lvl, 0);
        } else {
            conv_mma<1, true, true><<<dim3(gx1, CDIM / BN, ns1), THREADS,
                                      SMEM_BYTES>>>(b1, nullptr, P, P, lengths,
                                                    lvl, ns1);
        }
        // ---- conv2 ----
        int M2 = BZ * Pout;
        int gx2 = (M2 + BM - 1) / BM;
        int ns2 = pick_nspl(M2);
        if (ns2 == 0) {
            conv_mma<2, false, false><<<dim3(gx2, CDIM / BN), THREADS,
                                        SMEM_BYTES>>>(b2, out + off, P, Pout,
                                                      lengths, lvl, 0);
        } else {
            conv_mma<2, false, true><<<dim3(gx2, CDIM / BN, ns2), THREADS,
                                       SMEM_BYTES>>>(b2, out + off, P, Pout,
                                                     lengths, lvl, ns2);
        }
        off += (long)BZ * Pout * CDIM + (long)BZ * Pout;
        P = Pout;
    }
}

// round 16
// speedup vs baseline: 1.2666x; 1.2666x over previous
#include <cuda_runtime.h>
#include <cuda_bf16.h>
#include <math.h>
#include <cstdint>

// ---------------------------------------------------------------------------
// TreeGetter: 11-level conv halving tree as implicit GEMM on mma.sync (bf16,
// hi/lo 3-product split). 128-thread CTA (4 warps, 2Mx2N of 64x32 warp tiles),
// block 128x64x32, 2-stage XOR-swizzled smem, <=128 regs, 4 CTAs/SM.
// Split-K with SEPARATE highly-parallel reduce kernels (fused last-CTA
// reduction regressed: reduce parallelism must not scale with 1/nspl).
// M=4096 levels now split ns=3 (path 72 -> ~47).
// ---------------------------------------------------------------------------

#define CDIM 768
#define CK   2304
#define NLEV 11
#define BZ   16
#define BM   128
#define BN   64
#define BKC  32
#define NCH  (CK / BKC)      // 72
#define THREADS 128

#define A_BYTES 8192         // 128 rows * 64 B (swizzled, no pad), per plane
#define B_BYTES 4096         // 32 rows * 128 B (swizzled, no pad), per plane
#define STAGE_BYTES (2 * A_BYTES + 2 * B_BYTES)  // 24576
#define SMEM_BYTES (2 * STAGE_BYTES)             // 49152

// ---------------- scratch (device globals; allocation-free rule) ------------
#define MAXE ((long)BZ * 2048 * CDIM)
__device__ __nv_bfloat16 g_xhi[MAXE], g_xlo[MAXE];   // conv1 input splits
__device__ __nv_bfloat16 g_hhi[MAXE], g_hlo[MAXE];   // conv2 input splits
__device__ __nv_bfloat16 g_w1hi[CK * CDIM], g_w1lo[CK * CDIM];
__device__ __nv_bfloat16 g_w2hi[CK * CDIM], g_w2lo[CK * CDIM];
__device__ float g_part[(long)24576 * CDIM];         // split-K partials

__device__ __forceinline__ void split_bf16(float v, __nv_bfloat16& hi,
                                           __nv_bfloat16& lo) {
    hi = __float2bfloat16(v);
    lo = __float2bfloat16(v - __bfloat162float(hi));
}

__device__ __forceinline__ uint32_t smem_u32(const void* p) {
    uint32_t a;
    asm("{ .reg .u64 t; cvta.to.shared.u64 t, %1; cvt.u32.u64 %0, t; }"
        : "=r"(a) : "l"(p));
    return a;
}
__device__ __forceinline__ void cp_async16(uint32_t dst, const void* src,
                                           bool pred) {
    int sz = pred ? 16 : 0;
    asm volatile("cp.async.cg.shared.global [%0], [%1], 16, %2;"
                 :: "r"(dst), "l"(src), "r"(sz));
}
__device__ __forceinline__ void cp_commit() {
    asm volatile("cp.async.commit_group;");
}
__device__ __forceinline__ void ldsm_x4(uint32_t* r, uint32_t a) {
    asm volatile("ldmatrix.sync.aligned.m8n8.x4.shared.b16 {%0,%1,%2,%3}, [%4];"
                 : "=r"(r[0]), "=r"(r[1]), "=r"(r[2]), "=r"(r[3]) : "r"(a));
}
__device__ __forceinline__ void ldsm_x4_t(uint32_t* r, uint32_t a) {
    asm volatile("ldmatrix.sync.aligned.m8n8.x4.trans.shared.b16 {%0,%1,%2,%3}, [%4];"
                 : "=r"(r[0]), "=r"(r[1]), "=r"(r[2]), "=r"(r[3]) : "r"(a));
}
__device__ __forceinline__ void mma16816(float* d, const uint32_t* a,
                                         const uint32_t* b) {
    asm("mma.sync.aligned.m16n8k16.row.col.f32.bf16.bf16.f32 "
        "{%0,%1,%2,%3}, {%4,%5,%6,%7}, {%8,%9}, {%0,%1,%2,%3};"
        : "+f"(d[0]), "+f"(d[1]), "+f"(d[2]), "+f"(d[3])
        : "r"(a[0]), "r"(a[1]), "r"(a[2]), "r"(a[3]), "r"(b[0]), "r"(b[1]));
}
__device__ __forceinline__ float gelu_exact(float z) {
    return 0.5f * z * (1.f + erff(z * 0.70710678118654752f));
}

// ---------------------------------------------------------------------------
__global__ void prep_weights(const float* __restrict__ w1,
                             const float* __restrict__ w2) {
    int total = CK * CDIM;
    for (int j = blockIdx.x * blockDim.x + threadIdx.x; j < total;
         j += gridDim.x * blockDim.x) {
        int o  = j % CDIM;
        int kg = j / CDIM;
        int d  = kg / CDIM;
        int i  = kg - d * CDIM;
        long src = (long)o * CK + i * 3 + d;   // w[o][i][d]
        split_bf16(w1[src], g_w1hi[j], g_w1lo[j]);
        split_bf16(w2[src], g_w2hi[j], g_w2lo[j]);
    }
}

__global__ void prep_input(const float* __restrict__ seq,
                           const int* __restrict__ lengths) {
    long total = MAXE;
    for (long j = blockIdx.x * (long)blockDim.x + threadIdx.x; j < total;
         j += gridDim.x * (long)blockDim.x) {
        long bp = j / CDIM;
        int p = (int)(bp % 2048);
        int b = (int)(bp / 2048);
        float v = (p < lengths[b]) ? seq[j] : 0.f;
        split_bf16(v, g_xhi[j], g_xlo[j]);
    }
}

__global__ void mask_kernel(float* __restrict__ out,
                            const int* __restrict__ lengths) {
    int idx    = blockIdx.x * blockDim.x + threadIdx.x;
    int stride = gridDim.x * blockDim.x;
    long off = 0;
    int P = 2048;
    for (int lvl = 0; lvl < NLEV; lvl++) {
        int Pout = (P - 1) / 2 + 1;
        long maskOff = off + (long)BZ * Pout * CDIM;
        int n = BZ * Pout;
        for (int i = idx; i < n; i += stride) {
            int b = i / Pout, p = i % Pout;
            int L = lengths[b];
            for (int t = 0; t <= lvl; t++) L = (L - 1) / 2 + 1;
            out[maskOff + i] = (p < L) ? 1.f : 0.f;
        }
        off = maskOff + n;
        P = Pout;
    }
}

// ---------------------------------------------------------------------------
// reduce for split-K: sum nspl planes + bias (+gelu) + mask, write bf16 splits.
template <bool DO_GELU>
__global__ void reduce_split(const float* __restrict__ bias,
                             float* __restrict__ outY, int Pout,
                             const int* __restrict__ lengths, int level,
                             int Mtot, int nspl) {
    long total = (long)Mtot * (CDIM / 2);
    long plane = (long)Mtot * CDIM;
    for (long i = blockIdx.x * (long)blockDim.x + threadIdx.x; i < total;
         i += gridDim.x * (long)blockDim.x) {
        int row = (int)(i / (CDIM / 2));
        int col = (int)(i % (CDIM / 2)) * 2;
        int b = row / Pout, p = row - b * Pout;
        int L = lengths[b];
        for (int t = 0; t < level; t++) L = (L - 1) / 2 + 1;
        int lenOut = DO_GELU ? L : ((L - 1) / 2 + 1);
        float z0 = 0.f, z1 = 0.f;
        if (p < lenOut) {
            long off = (long)row * CDIM + col;
            for (int s = 0; s < nspl; s++) {
                float2 v = *(const float2*)(g_part + (long)s * plane + off);
                z0 += v.x;
                z1 += v.y;
            }
            z0 += __ldg(&bias[col]);
            z1 += __ldg(&bias[col + 1]);
            if (DO_GELU) { z0 = gelu_exact(z0); z1 = gelu_exact(z1); }
        }
        __nv_bfloat162 h2, l2;
        split_bf16(z0, h2.x, l2.x);
        split_bf16(z1, h2.y, l2.y);
        long base = (long)row * CDIM + col;
        if (DO_GELU) {
            *(__nv_bfloat162*)(g_hhi + base) = h2;
            *(__nv_bfloat162*)(g_hlo + base) = l2;
        } else {
            *(float2*)(outY + base) = make_float2(z0, z1);
            *(__nv_bfloat162*)(g_xhi + base) = h2;
            *(__nv_bfloat162*)(g_xlo + base) = l2;
        }
    }
}

// ---------------------------------------------------------------------------
// Implicit-GEMM conv on mma.sync.  128 threads = 4 warps (2M x 2N), warp
// tile 64x32, block 128x64x32, 2-stage XOR-swizzled buffer, 4 CTAs/SM.
// A swizzle: 64B rows, chunk ^= (row>>1)&3.  B swizzle: 128B rows, chunk ^= row&7.
template <int STRIDE, bool DO_GELU, bool SPLITK>
__global__ void __launch_bounds__(THREADS, 4)
conv_mma(const float* __restrict__ bias, float* __restrict__ outY,
         int Pin, int Pout, const int* __restrict__ lengths, int level,
         int nspl) {
    extern __shared__ char smem[];
    const uint32_t sbase = smem_u32(smem);
    const int tid   = threadIdx.x;
    const int lane  = tid & 31;
    const int wid   = tid >> 5;
    const int warpM = (wid & 1) * 64;
    const int warpN = (wid >> 1) * 32;
    const int p0    = blockIdx.x * BM;
    const int n0    = blockIdx.y * BN;
    const int Mtot  = BZ * Pout;
    const int NC     = SPLITK ? (NCH / nspl) : NCH;
    const int itBase = SPLITK ? (int)blockIdx.z * NC : 0;

    const __nv_bfloat16* Xhi = DO_GELU ? g_xhi : g_hhi;
    const __nv_bfloat16* Xlo = DO_GELU ? g_xlo : g_hlo;
    const __nv_bfloat16* Whi = DO_GELU ? g_w1hi : g_w2hi;
    const __nv_bfloat16* Wlo = DO_GELU ? g_w1lo : g_w2lo;

    float acc[4][4][4];
#pragma unroll
    for (int a = 0; a < 4; a++)
#pragma unroll
        for (int b = 0; b < 4; b++)
#pragma unroll
            for (int c = 0; c < 4; c++) acc[a][b][c] = 0.f;

    // ---- full-masked tile skip ----
    bool anyValid = false;
    {
        int bA = p0 / Pout;
        int bB = (p0 + BM - 1) / Pout;
        if (bB >= BZ) bB = BZ - 1;
        for (int b = bA; b <= bB; b++) {
            int L = lengths[b];
            for (int t = 0; t < level; t++) L = (L - 1) / 2 + 1;
            int lenOut = DO_GELU ? L : ((L - 1) / 2 + 1);
            int pstart = p0 > b * Pout ? p0 - b * Pout : 0;
            if (pstart < lenOut) { anyValid = true; break; }
        }
    }

    if (anyValid) {
        // ---- per-thread load geometry ----
        int aPosB[4]; long aRowBase[4]; bool aOk[4];
        const int akc = tid & 3;
#pragma unroll
        for (int i = 0; i < 4; i++) {
            int r = (tid + i * THREADS) >> 2;
            int grow = p0 + r;
            bool ok = grow < Mtot;
            int b = ok ? grow / Pout : 0;
            int p = grow - b * Pout;
            aOk[i] = ok;
            aPosB[i] = p * STRIDE - 1;
            aRowBase[i] = (long)b * Pin;
        }
        const int bnc = tid & 7;

        auto load_stage = [&](int slot, int it) {
            const uint32_t sa = sbase + slot * STAGE_BYTES;
            const int kk = it * BKC;
            const int d  = (kk >= 1536) ? 2 : (kk >= 768 ? 1 : 0);
            const int c0 = kk - d * CDIM;
#pragma unroll
            for (int i = 0; i < 4; i++) {
                int row = (tid + i * THREADS) >> 2;
                int pos = aPosB[i] + d;
                bool v = aOk[i] && pos >= 0 && pos < Pin;
                long g = v ? ((aRowBase[i] + pos) * CDIM + c0 + akc * 8) : 0;
                uint32_t dst = sa + row * 64 +
                               ((akc ^ ((row >> 1) & 3)) << 4);
                cp_async16(dst, Xhi + g, v);
                cp_async16(dst + A_BYTES, Xlo + g, v);
            }
#pragma unroll
            for (int i = 0; i < 2; i++) {
                int krow = (tid + i * THREADS) >> 3;
                long g = (long)(kk + krow) * CDIM + n0 + bnc * 8;
                uint32_t dst = sa + 2 * A_BYTES + krow * 128 +
                               ((bnc ^ (krow & 7)) << 4);
                cp_async16(dst, Whi + g, true);
                cp_async16(dst + B_BYTES, Wlo + g, true);
            }
            cp_commit();
        };

        const int alr = lane & 15;    // row-within-16 for A ldsm
        const int ahc = lane >> 4;    // chunk half-select
        uint32_t bh[2][4], bl[2][4];

        auto ldsm_b = [&](uint32_t sa, int ks) {
            int krow = ks + alr;
            uint32_t rb = sa + 2 * A_BYTES + krow * 128;
            int cb = (warpN >> 3) + ahc;
#pragma unroll
            for (int np = 0; np < 2; np++) {
                int c = cb + np * 2;
                uint32_t ad = rb + (((c ^ (krow & 7))) << 4);
                ldsm_x4_t(bh[np], ad);
                ldsm_x4_t(bl[np], ad + B_BYTES);
            }
        };
        // 12 MMAs for one mt row using freshly loaded A frags
        auto do_mt = [&](uint32_t sa, int mt, int ks) {
            int row = warpM + alr + mt * 16;
            int chunk = ((ks >> 4) << 1) + ahc;
            uint32_t ad = sa + row * 64 + ((chunk ^ ((row >> 1) & 3)) << 4);
            uint32_t ah[4], al[4];
            ldsm_x4(ah, ad);
            ldsm_x4(al, ad + A_BYTES);
#pragma unroll
            for (int nt = 0; nt < 4; nt++)
                mma16816(acc[mt][nt], ah, &bh[nt >> 1][(nt & 1) * 2]);
#pragma unroll
            for (int nt = 0; nt < 4; nt++)
                mma16816(acc[mt][nt], ah, &bl[nt >> 1][(nt & 1) * 2]);
#pragma unroll
            for (int nt = 0; nt < 4; nt++)
                mma16816(acc[mt][nt], al, &bh[nt >> 1][(nt & 1) * 2]);
        };

        // ---- prologue (NC >= 2 always) ----
        load_stage(0, itBase + 0);
        load_stage(1, itBase + 1);

        // ---- main loop ----
#pragma unroll 1
        for (int li = 0; li < NC; li++) {
            asm volatile("cp.async.wait_group %0;" :: "n"(1));
            __syncthreads();
            const uint32_t sa = sbase + (li & 1) * STAGE_BYTES;
            ldsm_b(sa, 0);
#pragma unroll
            for (int mt = 0; mt < 4; mt++) do_mt(sa, mt, 0);
            ldsm_b(sa, 16);
#pragma unroll
            for (int mt = 0; mt < 4; mt++) do_mt(sa, mt, 16);
            __syncthreads();     // slot fully read by all warps
            if (li + 2 < NC) load_stage(li & 1, itBase + li + 2);
            else cp_commit();    // keep group count uniform
        }
    }

    // ---- epilogue ----
    const int mrow0 = p0 + warpM + (lane >> 2);
    const int colb  = n0 + warpN + 2 * (lane & 3);
    if (SPLITK) {
        if (!anyValid) return;   // reduce masks these rows anyway
        float* plane = g_part + (long)blockIdx.z * Mtot * CDIM;
#pragma unroll
        for (int mt = 0; mt < 4; mt++)
#pragma unroll
            for (int half = 0; half < 2; half++) {
                int row = mrow0 + mt * 16 + half * 8;
                if (row >= Mtot) continue;
                long base = (long)row * CDIM;
#pragma unroll
                for (int nt = 0; nt < 4; nt++) {
                    int col = colb + nt * 8;
                    *(float2*)(plane + base + col) =
                        make_float2(acc[mt][nt][half * 2], acc[mt][nt][half * 2 + 1]);
                }
            }
        return;
    }
#pragma unroll
    for (int mt = 0; mt < 4; mt++) {
#pragma unroll
        for (int half = 0; half < 2; half++) {
            int row = mrow0 + mt * 16 + half * 8;
            if (row >= Mtot) continue;
            int b = row / Pout;
            int p = row - b * Pout;
            int L = lengths[b];
            for (int t = 0; t < level; t++) L = (L - 1) / 2 + 1;
            int lenOut = DO_GELU ? L : ((L - 1) / 2 + 1);
            bool valid = (p < lenOut) && anyValid;
            long base = (long)row * CDIM;
#pragma unroll
            for (int nt = 0; nt < 4; nt++) {
                int col = colb + nt * 8;
                float z0 = 0.f, z1 = 0.f;
                if (valid) {
                    z0 = acc[mt][nt][half * 2 + 0] + __ldg(&bias[col]);
                    z1 = acc[mt][nt][half * 2 + 1] + __ldg(&bias[col + 1]);
                    if (DO_GELU) { z0 = gelu_exact(z0); z1 = gelu_exact(z1); }
                }
                __nv_bfloat162 h2, l2;
                split_bf16(z0, h2.x, l2.x);
                split_bf16(z1, h2.y, l2.y);
                if (DO_GELU) {
                    *(__nv_bfloat162*)(g_hhi + base + col) = h2;
                    *(__nv_bfloat162*)(g_hlo + base + col) = l2;
                } else {
                    float2 o2 = make_float2(z0, z1);
                    *(float2*)(outY + base + col) = o2;
                    *(__nv_bfloat162*)(g_xhi + base + col) = h2;
                    *(__nv_bfloat162*)(g_xlo + base + col) = l2;
                }
            }
        }
    }
}

// ---------------------------------------------------------------------------
// split depth (capacity ~592 concurrent CTAs, gy = 12). ns must divide 72,
// and NC = 72/ns must be >= 2.
static inline int pick_nspl(int M) {
    if (M > 4096)  return 0;
    if (M == 4096) return 3;     // 1152 CTAs, ~2 waves x 24 = 48 (vs 72)
    if (M == 2048) return 3;     // 576 CTAs, path 24
    if (M == 1024) return 6;     // 576 CTAs, path 12
    if (M == 512)  return 12;    // 576 CTAs, path 6
    if (M == 256)  return 24;    // 576 CTAs, path 3
    return 36;                   // M <= 128: path 2
}

extern "C" void kernel_launch(void* const* d_in, const int* in_sizes, int n_in,
                              void* d_out, int out_size) {
    const float* seq     = (const float*)d_in[0];
    const int*   lengths = (const int*)  d_in[1];
    const float* w1      = (const float*)d_in[2];
    const float* b1      = (const float*)d_in[3];
    const float* w2      = (const float*)d_in[4];
    const float* b2      = (const float*)d_in[5];
    float* out = (float*)d_out;

    cudaFuncSetAttribute(conv_mma<1, true, false>,
                         cudaFuncAttributeMaxDynamicSharedMemorySize, SMEM_BYTES);
    cudaFuncSetAttribute(conv_mma<2, false, false>,
                         cudaFuncAttributeMaxDynamicSharedMemorySize, SMEM_BYTES);
    cudaFuncSetAttribute(conv_mma<1, true, true>,
                         cudaFuncAttributeMaxDynamicSharedMemorySize, SMEM_BYTES);
    cudaFuncSetAttribute(conv_mma<2, false, true>,
                         cudaFuncAttributeMaxDynamicSharedMemorySize, SMEM_BYTES);

    prep_weights<<<256, 256>>>(w1, w2);
    prep_input<<<512, 256>>>(seq, lengths);
    mask_kernel<<<64, 256>>>(out, lengths);

    int P = 2048;
    long off = 0;
    for (int lvl = 0; lvl < NLEV; lvl++) {
        int Pout = (P - 1) / 2 + 1;
        // ---- conv1 ----
        int M1 = BZ * P;
        int gx1 = (M1 + BM - 1) / BM;
        int ns1 = pick_nspl(M1);
        if (ns1 == 0) {
            conv_mma<1, true, false><<<dim3(gx1, CDIM / BN), THREADS,
                                       SMEM_BYTES>>>(b1, nullptr, P, P,
                                                     lengths, lvl, 0);
        } else {
            conv_mma<1, true, true><<<dim3(gx1, CDIM / BN, ns1), THREADS,
                                      SMEM_BYTES>>>(b1, nullptr, P, P, lengths,
                                                    lvl, ns1);
            long pairs = (long)M1 * (CDIM / 2);
            int blocks = (int)((pairs + 255) / 256);
            if (blocks > 2048) blocks = 2048;
            reduce_split<true><<<blocks, 256>>>(b1, nullptr, P, lengths, lvl,
                                                M1, ns1);
        }
        // ---- conv2 ----
        int M2 = BZ * Pout;
        int gx2 = (M2 + BM - 1) / BM;
        int ns2 = pick_nspl(M2);
        if (ns2 == 0) {
            conv_mma<2, false, false><<<dim3(gx2, CDIM / BN), THREADS,
                                        SMEM_BYTES>>>(b2, out + off, P, Pout,
                                                      lengths, lvl, 0);
        } else {
            conv_mma<2, false, true><<<dim3(gx2, CDIM / BN, ns2), THREADS,
                                       SMEM_BYTES>>>(b2, nullptr, P, Pout,
                                                     lengths, lvl, ns2);
            long pairs = (long)M2 * (CDIM / 2);
            int blocks = (int)((pairs + 255) / 256);
            if (blocks > 2048) blocks = 2048;
            reduce_split<false><<<blocks, 256>>>(b2, out + off, Pout, lengths,
                                                 lvl, M2, ns2);
        }
        off += (long)BZ * Pout * CDIM + (long)BZ * Pout;
        P = Pout;
    }
}